// round 8
// baseline (speedup 1.0000x reference)
#include <cuda_runtime.h>
#include <cuda_bf16.h>

#define NUSERS 100000
#define NITEMS 50000
#define NNODES 150000
#define DIM 64

// ---------------- scratch (device globals: allocation-free) ----------------
__device__ float g_A[NNODES * DIM];    // layer-2 accumulation target
__device__ float g_B[NNODES * DIM];    // layer-1 accumulation target
__device__ int   g_is64;               // edge_index dtype flag

// ---------------- f32x2 packed helpers (sm_103a) ---------------------------
__device__ __forceinline__ unsigned long long dup2(float x) {
    unsigned long long r;
    asm("mov.b64 %0, {%1, %1};" : "=l"(r) : "f"(x));
    return r;
}
__device__ __forceinline__ void ffma2(unsigned long long& d,
                                      unsigned long long a,
                                      unsigned long long b) {
    asm("fma.rn.f32x2 %0, %1, %2, %0;" : "+l"(d) : "l"(a), "l"(b));
}
__device__ __forceinline__ float2 unpk(unsigned long long v) {
    float2 f;
    asm("mov.b64 {%0, %1}, %2;" : "=f"(f.x), "=f"(f.y) : "l"(v));
    return f;
}

// ---------------- zero both buffers + dtype probe --------------------------
__global__ void k_zero(const long long* __restrict__ ei_probe)
{
    if (blockIdx.x == 0 && threadIdx.x == 0) {
        int is64 = 1;
        for (int i = 0; i < 64; i++) {
            long long v = ei_probe[i];
            if (v < 0 || v >= (long long)NNODES) { is64 = 0; break; }
        }
        g_is64 = is64;
    }
    const int total4 = NNODES * DIM / 4;
    float4* A4 = reinterpret_cast<float4*>(g_A);
    float4* B4 = reinterpret_cast<float4*>(g_B);
    const float4 z = make_float4(0.f, 0.f, 0.f, 0.f);
    for (int i = blockIdx.x * blockDim.x + threadIdx.x; i < total4;
         i += gridDim.x * blockDim.x) {
        A4[i] = z;
        B4[i] = z;
    }
}

// ------------- edge scatter: 4 edges / thread, 16 threads / edge -----------
// layer 0: gather users/items (virtual concat) -> RED into B
// layer 1: gather relu(B) -> RED into A
__global__ void k_scatter(const void* __restrict__ ei_raw,
                          const float* __restrict__ w,
                          const float* __restrict__ users,
                          const float* __restrict__ items,
                          int E, int Eq, int layer)
{
    int tid = blockIdx.x * blockDim.x + threadIdx.x;
    int eq = tid >> 4;
    if (eq >= Eq) return;
    const int c = (tid & 15) << 2;     // float offset within 64-wide row

    int e[4];
    bool ok[4];
#pragma unroll
    for (int i = 0; i < 4; i++) { e[i] = eq + i * Eq; ok[i] = (e[i] < E); }

    int s[4], d[4];
    if (g_is64) {
        const long long* ei = reinterpret_cast<const long long*>(ei_raw);
#pragma unroll
        for (int i = 0; i < 4; i++) {
            s[i] = ok[i] ? (int)ei[e[i]] : 0;
            d[i] = ok[i] ? (int)ei[E + e[i]] : 0;
        }
    } else {
        const int* ei = reinterpret_cast<const int*>(ei_raw);
#pragma unroll
        for (int i = 0; i < 4; i++) {
            s[i] = ok[i] ? ei[e[i]] : 0;
            d[i] = ok[i] ? ei[E + e[i]] : 0;
        }
    }

    float wt[4];
#pragma unroll
    for (int i = 0; i < 4; i++) wt[i] = ok[i] ? __ldg(w + e[i]) : 0.f;

    float4 v[4];
    float* dstE;
    if (layer == 0) {
#pragma unroll
        for (int i = 0; i < 4; i++) {
            const float* p = (s[i] < NUSERS)
                ? (users + (size_t)s[i] * DIM)
                : (items + (size_t)(s[i] - NUSERS) * DIM);
            v[i] = *reinterpret_cast<const float4*>(p + c);
        }
        dstE = g_B;
    } else {
#pragma unroll
        for (int i = 0; i < 4; i++)
            v[i] = *reinterpret_cast<const float4*>(g_B + (size_t)s[i] * DIM + c);
#pragma unroll
        for (int i = 0; i < 4; i++) {
            v[i].x = fmaxf(v[i].x, 0.f); v[i].y = fmaxf(v[i].y, 0.f);
            v[i].z = fmaxf(v[i].z, 0.f); v[i].w = fmaxf(v[i].w, 0.f);
        }
        dstE = g_A;
    }

#pragma unroll
    for (int i = 0; i < 4; i++) {
        if (!ok[i]) continue;
        float* p = dstE + (size_t)d[i] * DIM + c;
        asm volatile("red.global.add.v4.f32 [%0], {%1,%2,%3,%4};"
                     :: "l"(p), "f"(v[i].x * wt[i]), "f"(v[i].y * wt[i]),
                        "f"(v[i].z * wt[i]), "f"(v[i].w * wt[i]) : "memory");
    }
}

// ------- final: a = (orig + relu(B) + relu(A))/3; out = a@W^T + b ----------
// 128-row x 64-col block tile; thread tile 8 rows x 4 cols (2 f32x2 col
// pairs). fma.rn.f32x2 halves fma-pipe issue; col pairs come free from the
// wv LDS.128; row element dup via mov.b64 {a,a} runs on the alu pipe.
__global__ void __launch_bounds__(256)
k_final(const float* __restrict__ W, const float* __restrict__ b,
        const float* __restrict__ users, const float* __restrict__ items,
        float* __restrict__ out)
{
    __shared__ float Wt[DIM][DIM + 4];      // Wt[k][j] = W[j][k]
    __shared__ float aT[DIM][128 + 4];      // aT[k][rowL]
    __shared__ float sb[DIM];

    const int t = threadIdx.x;
    for (int idx = t; idx < DIM * DIM; idx += 256) {
        int j = idx >> 6, k = idx & 63;
        Wt[k][j] = W[idx];
    }
    if (t < DIM) sb[t] = b[t];

    const int base = blockIdx.x * 128;

    // ---- load phase: 2 threads per row, 32 cols (8 float4 groups) each ----
    {
        const int rowL = t & 127;           // warp lanes: 32 consecutive rows
        const int half = t >> 7;            // 0 or 1
        const int row  = base + rowL;
        const int cb   = half * 32;
        if (row < NNODES) {
            const float* orig_row = (row < NUSERS)
                ? users + (size_t)row * DIM
                : items + (size_t)(row - NUSERS) * DIM;
            float* copy_dst = (row < NUSERS)
                ? out + (size_t)NUSERS * DIM + (size_t)row * DIM
                : out + (size_t)2 * NUSERS * DIM + (size_t)NITEMS * DIM
                      + (size_t)(row - NUSERS) * DIM;
#pragma unroll
            for (int g = 0; g < 8; g++) {
                const int col = cb + 4 * g;
                float4 o  = *reinterpret_cast<const float4*>(orig_row + col);
                float4 va = *reinterpret_cast<const float4*>(
                                g_A + (size_t)row * DIM + col);
                float4 vb = *reinterpret_cast<const float4*>(
                                g_B + (size_t)row * DIM + col);
                aT[col + 0][rowL] =
                    (o.x + fmaxf(vb.x, 0.f) + fmaxf(va.x, 0.f)) * (1.f / 3.f);
                aT[col + 1][rowL] =
                    (o.y + fmaxf(vb.y, 0.f) + fmaxf(va.y, 0.f)) * (1.f / 3.f);
                aT[col + 2][rowL] =
                    (o.z + fmaxf(vb.z, 0.f) + fmaxf(va.z, 0.f)) * (1.f / 3.f);
                aT[col + 3][rowL] =
                    (o.w + fmaxf(vb.w, 0.f) + fmaxf(va.w, 0.f)) * (1.f / 3.f);
                *reinterpret_cast<float4*>(copy_dst + col) = o;  // passthrough
            }
        } else {
#pragma unroll
            for (int g = 0; g < 8; g++) {
                const int col = cb + 4 * g;
                aT[col + 0][rowL] = 0.f;
                aT[col + 1][rowL] = 0.f;
                aT[col + 2][rowL] = 0.f;
                aT[col + 3][rowL] = 0.f;
            }
        }
    }
    __syncthreads();

    // ---- compute phase: thread (ri, ci) -> rows 8ri..+7, cols 4ci..+3 ----
    const int ri = t >> 4;                  // 0..15
    const int ci = t & 15;                  // 0..15

    unsigned long long acc[8][2];
#pragma unroll
    for (int r = 0; r < 8; r++) { acc[r][0] = 0ull; acc[r][1] = 0ull; }

#pragma unroll 8
    for (int k = 0; k < DIM; k++) {
        float4 a0 = *reinterpret_cast<const float4*>(&aT[k][8 * ri]);
        float4 a1 = *reinterpret_cast<const float4*>(&aT[k][8 * ri + 4]);
        float4 wv = *reinterpret_cast<const float4*>(&Wt[k][4 * ci]);
        unsigned long long w01, w23;
        asm("mov.b64 %0, {%1, %2};" : "=l"(w01) : "f"(wv.x), "f"(wv.y));
        asm("mov.b64 %0, {%1, %2};" : "=l"(w23) : "f"(wv.z), "f"(wv.w));

        unsigned long long ad;
        ad = dup2(a0.x); ffma2(acc[0][0], ad, w01); ffma2(acc[0][1], ad, w23);
        ad = dup2(a0.y); ffma2(acc[1][0], ad, w01); ffma2(acc[1][1], ad, w23);
        ad = dup2(a0.z); ffma2(acc[2][0], ad, w01); ffma2(acc[2][1], ad, w23);
        ad = dup2(a0.w); ffma2(acc[3][0], ad, w01); ffma2(acc[3][1], ad, w23);
        ad = dup2(a1.x); ffma2(acc[4][0], ad, w01); ffma2(acc[4][1], ad, w23);
        ad = dup2(a1.y); ffma2(acc[5][0], ad, w01); ffma2(acc[5][1], ad, w23);
        ad = dup2(a1.z); ffma2(acc[6][0], ad, w01); ffma2(acc[6][1], ad, w23);
        ad = dup2(a1.w); ffma2(acc[7][0], ad, w01); ffma2(acc[7][1], ad, w23);
    }

    const float4 bias = *reinterpret_cast<const float4*>(&sb[4 * ci]);
#pragma unroll
    for (int r = 0; r < 8; r++) {
        const int row = base + 8 * ri + r;
        if (row >= NNODES) break;
        float2 p0 = unpk(acc[r][0]);
        float2 p1 = unpk(acc[r][1]);
        float4 s;
        s.x = p0.x + bias.x;
        s.y = p0.y + bias.y;
        s.z = p1.x + bias.z;
        s.w = p1.y + bias.w;
        float* dst = (row < NUSERS)
            ? out + (size_t)row * DIM
            : out + (size_t)2 * NUSERS * DIM + (size_t)(row - NUSERS) * DIM;
        *reinterpret_cast<float4*>(dst + 4 * ci) = s;
    }
}

// ---------------------------------------------------------------------------
extern "C" void kernel_launch(void* const* d_in, const int* in_sizes, int n_in,
                              void* d_out, int out_size)
{
    const void*  ei    = d_in[0];
    const float* w     = (const float*)d_in[1];
    const float* users = (const float*)d_in[2];
    const float* items = (const float*)d_in[3];
    const float* W     = (const float*)d_in[4];
    const float* b     = (const float*)d_in[5];
    float* out = (float*)d_out;

    const int E  = in_sizes[1];       // edge_weight element count
    const int Eq = (E + 3) / 4;

    k_zero<<<2048, 256>>>((const long long*)ei);

    int sblocks = (Eq * 16 + 255) / 256;
    k_scatter<<<sblocks, 256>>>(ei, w, users, items, E, Eq, 0); // inputs -> B
    k_scatter<<<sblocks, 256>>>(ei, w, users, items, E, Eq, 1); // relu(B) -> A

    k_final<<<(NNODES + 127) / 128, 256>>>(W, b, users, items, out);
}

// round 9
// speedup vs baseline: 1.0990x; 1.0990x over previous
#include <cuda_runtime.h>
#include <cuda_bf16.h>

#define NUSERS 100000
#define NITEMS 50000
#define NNODES 150000
#define DIM 64

// ---------------- scratch (device globals: allocation-free) ----------------
__device__ float g_A[NNODES * DIM];    // layer-2 accumulation target
__device__ float g_B[NNODES * DIM];    // layer-1 accumulation target
__device__ int   g_is64;               // edge_index dtype flag

// ---------------- zero both buffers + dtype probe --------------------------
__global__ void k_zero(const long long* __restrict__ ei_probe)
{
    if (blockIdx.x == 0 && threadIdx.x == 0) {
        int is64 = 1;
        for (int i = 0; i < 64; i++) {
            long long v = ei_probe[i];
            if (v < 0 || v >= (long long)NNODES) { is64 = 0; break; }
        }
        g_is64 = is64;
    }
    const int total4 = NNODES * DIM / 4;
    float4* A4 = reinterpret_cast<float4*>(g_A);
    float4* B4 = reinterpret_cast<float4*>(g_B);
    const float4 z = make_float4(0.f, 0.f, 0.f, 0.f);
    for (int i = blockIdx.x * blockDim.x + threadIdx.x; i < total4;
         i += gridDim.x * blockDim.x) {
        A4[i] = z;
        B4[i] = z;
    }
}

// ------------- edge scatter: 4 edges / thread, 16 threads / edge -----------
// layer 0: gather users/items (virtual concat) -> RED into B
// layer 1: gather relu(B) -> RED into A
__global__ void k_scatter(const void* __restrict__ ei_raw,
                          const float* __restrict__ w,
                          const float* __restrict__ users,
                          const float* __restrict__ items,
                          int E, int Eq, int layer)
{
    int tid = blockIdx.x * blockDim.x + threadIdx.x;
    int eq = tid >> 4;
    if (eq >= Eq) return;
    const int c = (tid & 15) << 2;     // float offset within 64-wide row

    int e[4];
    bool ok[4];
#pragma unroll
    for (int i = 0; i < 4; i++) { e[i] = eq + i * Eq; ok[i] = (e[i] < E); }

    int s[4], d[4];
    if (g_is64) {
        const long long* ei = reinterpret_cast<const long long*>(ei_raw);
#pragma unroll
        for (int i = 0; i < 4; i++) {
            s[i] = ok[i] ? (int)ei[e[i]] : 0;
            d[i] = ok[i] ? (int)ei[E + e[i]] : 0;
        }
    } else {
        const int* ei = reinterpret_cast<const int*>(ei_raw);
#pragma unroll
        for (int i = 0; i < 4; i++) {
            s[i] = ok[i] ? ei[e[i]] : 0;
            d[i] = ok[i] ? ei[E + e[i]] : 0;
        }
    }

    float wt[4];
#pragma unroll
    for (int i = 0; i < 4; i++) wt[i] = ok[i] ? __ldg(w + e[i]) : 0.f;

    float4 v[4];
    float* dstE;
    if (layer == 0) {
#pragma unroll
        for (int i = 0; i < 4; i++) {
            const float* p = (s[i] < NUSERS)
                ? (users + (size_t)s[i] * DIM)
                : (items + (size_t)(s[i] - NUSERS) * DIM);
            v[i] = *reinterpret_cast<const float4*>(p + c);
        }
        dstE = g_B;
    } else {
#pragma unroll
        for (int i = 0; i < 4; i++)
            v[i] = *reinterpret_cast<const float4*>(g_B + (size_t)s[i] * DIM + c);
#pragma unroll
        for (int i = 0; i < 4; i++) {
            v[i].x = fmaxf(v[i].x, 0.f); v[i].y = fmaxf(v[i].y, 0.f);
            v[i].z = fmaxf(v[i].z, 0.f); v[i].w = fmaxf(v[i].w, 0.f);
        }
        dstE = g_A;
    }

#pragma unroll
    for (int i = 0; i < 4; i++) {
        if (!ok[i]) continue;
        float* p = dstE + (size_t)d[i] * DIM + c;
        asm volatile("red.global.add.v4.f32 [%0], {%1,%2,%3,%4};"
                     :: "l"(p), "f"(v[i].x * wt[i]), "f"(v[i].y * wt[i]),
                        "f"(v[i].z * wt[i]), "f"(v[i].w * wt[i]) : "memory");
    }
}

// ------- final: a = (orig + relu(B) + relu(A))/3; out = a@W^T + b ----------
// 64-row x 64-col tile per block; 4x4 register tile per thread;
// float4 LDS for both operands (a stored transposed).  [round-7 version]
__global__ void __launch_bounds__(256)
k_final(const float* __restrict__ W, const float* __restrict__ b,
        const float* __restrict__ users, const float* __restrict__ items,
        float* __restrict__ out)
{
    __shared__ float Wt[DIM][DIM + 4];   // Wt[k][j] = W[j][k]; stride 68
    __shared__ float aT[DIM][DIM + 4];   // aT[k][rowL]; stride 68
    __shared__ float sb[DIM];

    const int t = threadIdx.x;
    for (int idx = t; idx < DIM * DIM; idx += 256) {
        int j = idx >> 6, k = idx & 63;
        Wt[k][j] = W[idx];
    }
    if (t < DIM) sb[t] = b[t];

    const int base = blockIdx.x * 64;

    // ---- load phase: 4 threads per row, 16 cols each ----
    {
        const int rowL  = t >> 2;
        const int row   = base + rowL;
        const int cbase = (t & 3) * 16;
        if (row < NNODES) {
            const float* orig_row = (row < NUSERS)
                ? users + (size_t)row * DIM
                : items + (size_t)(row - NUSERS) * DIM;
            float* copy_dst = (row < NUSERS)
                ? out + (size_t)NUSERS * DIM + (size_t)row * DIM
                : out + (size_t)2 * NUSERS * DIM + (size_t)NITEMS * DIM
                      + (size_t)(row - NUSERS) * DIM;
#pragma unroll
            for (int g = 0; g < 4; g++) {
                const int col = cbase + 4 * g;
                float4 o  = *reinterpret_cast<const float4*>(orig_row + col);
                float4 va = *reinterpret_cast<const float4*>(
                                g_A + (size_t)row * DIM + col);
                float4 vb = *reinterpret_cast<const float4*>(
                                g_B + (size_t)row * DIM + col);
                aT[col + 0][rowL] =
                    (o.x + fmaxf(vb.x, 0.f) + fmaxf(va.x, 0.f)) * (1.f / 3.f);
                aT[col + 1][rowL] =
                    (o.y + fmaxf(vb.y, 0.f) + fmaxf(va.y, 0.f)) * (1.f / 3.f);
                aT[col + 2][rowL] =
                    (o.z + fmaxf(vb.z, 0.f) + fmaxf(va.z, 0.f)) * (1.f / 3.f);
                aT[col + 3][rowL] =
                    (o.w + fmaxf(vb.w, 0.f) + fmaxf(va.w, 0.f)) * (1.f / 3.f);
                *reinterpret_cast<float4*>(copy_dst + col) = o;  // passthrough
            }
        } else {
#pragma unroll
            for (int g = 0; g < 4; g++) {
                const int col = cbase + 4 * g;
                aT[col + 0][rowL] = 0.f;
                aT[col + 1][rowL] = 0.f;
                aT[col + 2][rowL] = 0.f;
                aT[col + 3][rowL] = 0.f;
            }
        }
    }
    __syncthreads();

    // ---- compute phase: thread (ri, ci) -> rows 4ri..+3, cols 4ci..+3 ----
    const int ri = t >> 4;
    const int ci = t & 15;
    float acc[4][4] = {};

#pragma unroll
    for (int k = 0; k < DIM; k++) {
        float4 av = *reinterpret_cast<const float4*>(&aT[k][4 * ri]);
        float4 wv = *reinterpret_cast<const float4*>(&Wt[k][4 * ci]);
        acc[0][0] = fmaf(av.x, wv.x, acc[0][0]);
        acc[0][1] = fmaf(av.x, wv.y, acc[0][1]);
        acc[0][2] = fmaf(av.x, wv.z, acc[0][2]);
        acc[0][3] = fmaf(av.x, wv.w, acc[0][3]);
        acc[1][0] = fmaf(av.y, wv.x, acc[1][0]);
        acc[1][1] = fmaf(av.y, wv.y, acc[1][1]);
        acc[1][2] = fmaf(av.y, wv.z, acc[1][2]);
        acc[1][3] = fmaf(av.y, wv.w, acc[1][3]);
        acc[2][0] = fmaf(av.z, wv.x, acc[2][0]);
        acc[2][1] = fmaf(av.z, wv.y, acc[2][1]);
        acc[2][2] = fmaf(av.z, wv.z, acc[2][2]);
        acc[2][3] = fmaf(av.z, wv.w, acc[2][3]);
        acc[3][0] = fmaf(av.w, wv.x, acc[3][0]);
        acc[3][1] = fmaf(av.w, wv.y, acc[3][1]);
        acc[3][2] = fmaf(av.w, wv.z, acc[3][2]);
        acc[3][3] = fmaf(av.w, wv.w, acc[3][3]);
    }

    const float4 bias = *reinterpret_cast<const float4*>(&sb[4 * ci]);
#pragma unroll
    for (int r = 0; r < 4; r++) {
        const int row = base + 4 * ri + r;
        if (row >= NNODES) break;
        float4 s;
        s.x = acc[r][0] + bias.x;
        s.y = acc[r][1] + bias.y;
        s.z = acc[r][2] + bias.z;
        s.w = acc[r][3] + bias.w;
        float* dst = (row < NUSERS)
            ? out + (size_t)row * DIM
            : out + (size_t)2 * NUSERS * DIM + (size_t)(row - NUSERS) * DIM;
        *reinterpret_cast<float4*>(dst + 4 * ci) = s;
    }
}

// ---------------------------------------------------------------------------
extern "C" void kernel_launch(void* const* d_in, const int* in_sizes, int n_in,
                              void* d_out, int out_size)
{
    const void*  ei    = d_in[0];
    const float* w     = (const float*)d_in[1];
    const float* users = (const float*)d_in[2];
    const float* items = (const float*)d_in[3];
    const float* W     = (const float*)d_in[4];
    const float* b     = (const float*)d_in[5];
    float* out = (float*)d_out;

    const int E  = in_sizes[1];       // edge_weight element count
    const int Eq = (E + 3) / 4;

    k_zero<<<2048, 256>>>((const long long*)ei);

    int sblocks = (Eq * 16 + 255) / 256;
    k_scatter<<<sblocks, 256>>>(ei, w, users, items, E, Eq, 0); // inputs -> B
    k_scatter<<<sblocks, 256>>>(ei, w, users, items, E, Eq, 1); // relu(B) -> A

    k_final<<<(NNODES + 63) / 64, 256>>>(W, b, users, items, out);
}

// round 11
// speedup vs baseline: 1.1899x; 1.0827x over previous
#include <cuda_runtime.h>
#include <cuda_bf16.h>

#define NUSERS 100000
#define NITEMS 50000
#define NNODES 150000
#define DIM 64
#define EMAX 2000000
#define NB ((NNODES + 255) / 256)   // 586 scan blocks

// ---------------- scratch (device globals: allocation-free) ----------------
__device__ float g_A[NNODES * DIM];   // layer-2 output (raw sums)
__device__ float g_B[NNODES * DIM];   // layer-1 output (raw sums)
__device__ int   g_deg[NNODES];       // per-dst degree
__device__ int   g_ptr[NNODES];       // CSR row start (exclusive prefix)
__device__ int   g_cur[NNODES];       // mutable cursor for permute
__device__ int2  g_csr[EMAX];         // (src, w_bits) grouped by dst
__device__ int   g_part[1024];        // scan partials
__device__ int   g_is64;              // edge_index dtype flag

// ---------------- zero degrees + dtype probe -------------------------------
__global__ void k_zero(const long long* __restrict__ ei_probe)
{
    int tid = blockIdx.x * blockDim.x + threadIdx.x;
    if (tid == 0) {
        int is64 = 1;
        for (int i = 0; i < 64; i++) {
            long long v = ei_probe[i];
            if (v < 0 || v >= (long long)NNODES) { is64 = 0; break; }
        }
        g_is64 = is64;
    }
    if (tid < NNODES) g_deg[tid] = 0;
}

// ---------------- histogram of dst -----------------------------------------
__global__ void k_hist(const void* __restrict__ ei_raw, int E)
{
    int e = blockIdx.x * blockDim.x + threadIdx.x;
    if (e >= E) return;
    int d;
    if (g_is64) d = (int)reinterpret_cast<const long long*>(ei_raw)[E + e];
    else        d = reinterpret_cast<const int*>(ei_raw)[E + e];
    atomicAdd(&g_deg[d], 1);
}

// ---------------- scan phase A: per-block partial sums ---------------------
__global__ void k_scanA()
{
    __shared__ int s[256];
    int t = threadIdx.x;
    int i = blockIdx.x * 256 + t;
    s[t] = (i < NNODES) ? g_deg[i] : 0;
    __syncthreads();
#pragma unroll
    for (int off = 128; off > 0; off >>= 1) {
        if (t < off) s[t] += s[t + off];
        __syncthreads();
    }
    if (t == 0) g_part[blockIdx.x] = s[0];
}

// ---------------- scan phase B: inclusive scan of partials (1 block) -------
__global__ void k_scanB()
{
    __shared__ int s[1024];
    int t = threadIdx.x;
    s[t] = (t < NB) ? g_part[t] : 0;
    __syncthreads();
    for (int off = 1; off < 1024; off <<= 1) {
        int v = (t >= off) ? s[t - off] : 0;
        __syncthreads();
        s[t] += v;
        __syncthreads();
    }
    if (t < NB) g_part[t] = s[t];   // inclusive partial sums
}

// ---------------- scan phase C: block scan + offset -> ptr, cursor ---------
__global__ void k_scanC()
{
    __shared__ int s[256];
    int t = threadIdx.x;
    int b = blockIdx.x;
    int i = b * 256 + t;
    int mine = (i < NNODES) ? g_deg[i] : 0;
    s[t] = mine;
    __syncthreads();
    for (int off = 1; off < 256; off <<= 1) {
        int v = (t >= off) ? s[t - off] : 0;
        __syncthreads();
        s[t] += v;
        __syncthreads();
    }
    int excl = s[t] - mine + ((b > 0) ? g_part[b - 1] : 0);
    if (i < NNODES) { g_ptr[i] = excl; g_cur[i] = excl; }
}

// ---------------- permute edges into dst-grouped (src, w) pairs ------------
__global__ void k_permute(const void* __restrict__ ei_raw,
                          const float* __restrict__ w, int E)
{
    int e = blockIdx.x * blockDim.x + threadIdx.x;
    if (e >= E) return;
    int s, d;
    if (g_is64) {
        const long long* ei = reinterpret_cast<const long long*>(ei_raw);
        s = (int)ei[e];  d = (int)ei[E + e];
    } else {
        const int* ei = reinterpret_cast<const int*>(ei_raw);
        s = ei[e];  d = ei[E + e];
    }
    float wt = __ldg(w + e);
    int pos = atomicAdd(&g_cur[d], 1);
    if (pos < EMAX) g_csr[pos] = make_int2(s, __float_as_int(wt));
}

// ---------------- segment sum: node = sum_e w_e * f(src row) ---------------
// layer 0: f = identity over users/items virtual concat  -> write g_B
// layer 1: f = relu over g_B                             -> write g_A
__global__ void k_seg(const float* __restrict__ users,
                      const float* __restrict__ items, int layer)
{
    int tid = blockIdx.x * blockDim.x + threadIdx.x;
    int node = tid >> 4;
    if (node >= NNODES) return;
    const int c = (tid & 15) << 2;

    const int beg = g_ptr[node];
    const int deg = g_deg[node];

    float4 acc = make_float4(0.f, 0.f, 0.f, 0.f);
    int i = 0;
    for (; i + 2 <= deg; i += 2) {
        int2 e0 = g_csr[beg + i];
        int2 e1 = g_csr[beg + i + 1];
        float4 v0, v1;
        if (layer == 0) {
            const float* p0 = (e0.x < NUSERS)
                ? users + (size_t)e0.x * DIM
                : items + (size_t)(e0.x - NUSERS) * DIM;
            const float* p1 = (e1.x < NUSERS)
                ? users + (size_t)e1.x * DIM
                : items + (size_t)(e1.x - NUSERS) * DIM;
            v0 = *reinterpret_cast<const float4*>(p0 + c);
            v1 = *reinterpret_cast<const float4*>(p1 + c);
        } else {
            v0 = *reinterpret_cast<const float4*>(g_B + (size_t)e0.x * DIM + c);
            v1 = *reinterpret_cast<const float4*>(g_B + (size_t)e1.x * DIM + c);
            v0.x = fmaxf(v0.x, 0.f); v0.y = fmaxf(v0.y, 0.f);
            v0.z = fmaxf(v0.z, 0.f); v0.w = fmaxf(v0.w, 0.f);
            v1.x = fmaxf(v1.x, 0.f); v1.y = fmaxf(v1.y, 0.f);
            v1.z = fmaxf(v1.z, 0.f); v1.w = fmaxf(v1.w, 0.f);
        }
        float w0 = __int_as_float(e0.y);
        float w1 = __int_as_float(e1.y);
        acc.x = fmaf(v0.x, w0, acc.x); acc.y = fmaf(v0.y, w0, acc.y);
        acc.z = fmaf(v0.z, w0, acc.z); acc.w = fmaf(v0.w, w0, acc.w);
        acc.x = fmaf(v1.x, w1, acc.x); acc.y = fmaf(v1.y, w1, acc.y);
        acc.z = fmaf(v1.z, w1, acc.z); acc.w = fmaf(v1.w, w1, acc.w);
    }
    if (i < deg) {
        int2 e0 = g_csr[beg + i];
        float4 v0;
        if (layer == 0) {
            const float* p0 = (e0.x < NUSERS)
                ? users + (size_t)e0.x * DIM
                : items + (size_t)(e0.x - NUSERS) * DIM;
            v0 = *reinterpret_cast<const float4*>(p0 + c);
        } else {
            v0 = *reinterpret_cast<const float4*>(g_B + (size_t)e0.x * DIM + c);
            v0.x = fmaxf(v0.x, 0.f); v0.y = fmaxf(v0.y, 0.f);
            v0.z = fmaxf(v0.z, 0.f); v0.w = fmaxf(v0.w, 0.f);
        }
        float w0 = __int_as_float(e0.y);
        acc.x = fmaf(v0.x, w0, acc.x); acc.y = fmaf(v0.y, w0, acc.y);
        acc.z = fmaf(v0.z, w0, acc.z); acc.w = fmaf(v0.w, w0, acc.w);
    }

    float* dst = layer ? g_A : g_B;
    *reinterpret_cast<float4*>(dst + (size_t)node * DIM + c) = acc;
}

// ------- final: a = (orig + relu(B) + relu(A))/3; out = a@W^T + b ----------
// 64x64 tile per block; 4x4 register tile; float4 LDS both operands.
__global__ void __launch_bounds__(256)
k_final(const float* __restrict__ W, const float* __restrict__ b,
        const float* __restrict__ users, const float* __restrict__ items,
        float* __restrict__ out)
{
    __shared__ float Wt[DIM][DIM + 4];
    __shared__ float aT[DIM][DIM + 4];
    __shared__ float sb[DIM];

    const int t = threadIdx.x;
    for (int idx = t; idx < DIM * DIM; idx += 256) {
        int j = idx >> 6, k = idx & 63;
        Wt[k][j] = W[idx];
    }
    if (t < DIM) sb[t] = b[t];

    const int base = blockIdx.x * 64;

    {
        const int rowL  = t >> 2;
        const int row   = base + rowL;
        const int cbase = (t & 3) * 16;
        if (row < NNODES) {
            const float* orig_row = (row < NUSERS)
                ? users + (size_t)row * DIM
                : items + (size_t)(row - NUSERS) * DIM;
            float* copy_dst = (row < NUSERS)
                ? out + (size_t)NUSERS * DIM + (size_t)row * DIM
                : out + (size_t)2 * NUSERS * DIM + (size_t)NITEMS * DIM
                      + (size_t)(row - NUSERS) * DIM;
#pragma unroll
            for (int g = 0; g < 4; g++) {
                const int col = cbase + 4 * g;
                float4 o  = *reinterpret_cast<const float4*>(orig_row + col);
                float4 va = *reinterpret_cast<const float4*>(
                                g_A + (size_t)row * DIM + col);
                float4 vb = *reinterpret_cast<const float4*>(
                                g_B + (size_t)row * DIM + col);
                aT[col + 0][rowL] =
                    (o.x + fmaxf(vb.x, 0.f) + fmaxf(va.x, 0.f)) * (1.f / 3.f);
                aT[col + 1][rowL] =
                    (o.y + fmaxf(vb.y, 0.f) + fmaxf(va.y, 0.f)) * (1.f / 3.f);
                aT[col + 2][rowL] =
                    (o.z + fmaxf(vb.z, 0.f) + fmaxf(va.z, 0.f)) * (1.f / 3.f);
                aT[col + 3][rowL] =
                    (o.w + fmaxf(vb.w, 0.f) + fmaxf(va.w, 0.f)) * (1.f / 3.f);
                *reinterpret_cast<float4*>(copy_dst + col) = o;  // passthrough
            }
        } else {
#pragma unroll
            for (int g = 0; g < 4; g++) {
                const int col = cbase + 4 * g;
                aT[col + 0][rowL] = 0.f;
                aT[col + 1][rowL] = 0.f;
                aT[col + 2][rowL] = 0.f;
                aT[col + 3][rowL] = 0.f;
            }
        }
    }
    __syncthreads();

    const int ri = t >> 4;
    const int ci = t & 15;
    float acc[4][4] = {};

#pragma unroll
    for (int k = 0; k < DIM; k++) {
        float4 av = *reinterpret_cast<const float4*>(&aT[k][4 * ri]);
        float4 wv = *reinterpret_cast<const float4*>(&Wt[k][4 * ci]);
        acc[0][0] = fmaf(av.x, wv.x, acc[0][0]);
        acc[0][1] = fmaf(av.x, wv.y, acc[0][1]);
        acc[0][2] = fmaf(av.x, wv.z, acc[0][2]);
        acc[0][3] = fmaf(av.x, wv.w, acc[0][3]);
        acc[1][0] = fmaf(av.y, wv.x, acc[1][0]);
        acc[1][1] = fmaf(av.y, wv.y, acc[1][1]);
        acc[1][2] = fmaf(av.y, wv.z, acc[1][2]);
        acc[1][3] = fmaf(av.y, wv.w, acc[1][3]);
        acc[2][0] = fmaf(av.z, wv.x, acc[2][0]);
        acc[2][1] = fmaf(av.z, wv.y, acc[2][1]);
        acc[2][2] = fmaf(av.z, wv.z, acc[2][2]);
        acc[2][3] = fmaf(av.z, wv.w, acc[2][3]);
        acc[3][0] = fmaf(av.w, wv.x, acc[3][0]);
        acc[3][1] = fmaf(av.w, wv.y, acc[3][1]);
        acc[3][2] = fmaf(av.w, wv.z, acc[3][2]);
        acc[3][3] = fmaf(av.w, wv.w, acc[3][3]);
    }

    const float4 bias = *reinterpret_cast<const float4*>(&sb[4 * ci]);
#pragma unroll
    for (int r = 0; r < 4; r++) {
        const int row = base + 4 * ri + r;
        if (row >= NNODES) break;
        float4 s;
        s.x = acc[r][0] + bias.x;
        s.y = acc[r][1] + bias.y;
        s.z = acc[r][2] + bias.z;
        s.w = acc[r][3] + bias.w;
        float* dst = (row < NUSERS)
            ? out + (size_t)row * DIM
            : out + (size_t)2 * NUSERS * DIM + (size_t)(row - NUSERS) * DIM;
        *reinterpret_cast<float4*>(dst + 4 * ci) = s;
    }
}

// ---------------------------------------------------------------------------
extern "C" void kernel_launch(void* const* d_in, const int* in_sizes, int n_in,
                              void* d_out, int out_size)
{
    const void*  ei    = d_in[0];
    const float* w     = (const float*)d_in[1];
    const float* users = (const float*)d_in[2];
    const float* items = (const float*)d_in[3];
    const float* W     = (const float*)d_in[4];
    const float* b     = (const float*)d_in[5];
    float* out = (float*)d_out;

    const int E = in_sizes[1];        // edge_weight element count

    const int eb = (E + 255) / 256;
    const int segb = (NNODES * 16 + 255) / 256;

    k_zero<<<(NNODES + 255) / 256, 256>>>((const long long*)ei);
    k_hist<<<eb, 256>>>(ei, E);
    k_scanA<<<NB, 256>>>();
    k_scanB<<<1, 1024>>>();
    k_scanC<<<NB, 256>>>();
    k_permute<<<eb, 256>>>(ei, w, E);

    k_seg<<<segb, 256>>>(users, items, 0);   // inputs  -> B (raw sums)
    k_seg<<<segb, 256>>>(users, items, 1);   // relu(B) -> A (raw sums)

    k_final<<<(NNODES + 63) / 64, 256>>>(W, b, users, items, out);
}

// round 12
// speedup vs baseline: 1.2032x; 1.0111x over previous
#include <cuda_runtime.h>
#include <cuda_bf16.h>

#define NUSERS 100000
#define NITEMS 50000
#define NNODES 150000
#define DIM 64
#define EMAX 2000000
#define NB ((NNODES + 255) / 256)   // 586 scan blocks

// ---------------- scratch (device globals: allocation-free) ----------------
__device__ float g_A[NNODES * DIM];   // layer-2 output (raw sums)
__device__ float g_B[NNODES * DIM];   // layer-1 output (raw sums)
__device__ int   g_deg[NNODES];       // per-dst degree
__device__ int   g_ptr[NNODES];       // CSR row start (exclusive prefix)
__device__ int   g_cur[NNODES];       // mutable cursor for permute
__device__ int2  g_csr[EMAX];         // (src, w_bits) grouped by dst
__device__ int   g_part[1024];        // scan partials
__device__ int   g_is64;              // edge_index dtype flag

// ---------------- zero degrees + dtype probe -------------------------------
__global__ void k_zero(const long long* __restrict__ ei_probe)
{
    int tid = blockIdx.x * blockDim.x + threadIdx.x;
    if (tid == 0) {
        int is64 = 1;
        for (int i = 0; i < 64; i++) {
            long long v = ei_probe[i];
            if (v < 0 || v >= (long long)NNODES) { is64 = 0; break; }
        }
        g_is64 = is64;
    }
    if (tid < NNODES) g_deg[tid] = 0;
}

// ---------------- histogram of dst -----------------------------------------
__global__ void k_hist(const void* __restrict__ ei_raw, int E)
{
    int e = blockIdx.x * blockDim.x + threadIdx.x;
    if (e >= E) return;
    int d;
    if (g_is64) d = (int)reinterpret_cast<const long long*>(ei_raw)[E + e];
    else        d = reinterpret_cast<const int*>(ei_raw)[E + e];
    atomicAdd(&g_deg[d], 1);
}

// ---------------- scan phase A: per-block partial sums ---------------------
__global__ void k_scanA()
{
    __shared__ int s[256];
    int t = threadIdx.x;
    int i = blockIdx.x * 256 + t;
    s[t] = (i < NNODES) ? g_deg[i] : 0;
    __syncthreads();
#pragma unroll
    for (int off = 128; off > 0; off >>= 1) {
        if (t < off) s[t] += s[t + off];
        __syncthreads();
    }
    if (t == 0) g_part[blockIdx.x] = s[0];
}

// ---------------- scan phase B: inclusive scan of partials (1 block) -------
__global__ void k_scanB()
{
    __shared__ int s[1024];
    int t = threadIdx.x;
    s[t] = (t < NB) ? g_part[t] : 0;
    __syncthreads();
    for (int off = 1; off < 1024; off <<= 1) {
        int v = (t >= off) ? s[t - off] : 0;
        __syncthreads();
        s[t] += v;
        __syncthreads();
    }
    if (t < NB) g_part[t] = s[t];   // inclusive partial sums
}

// ---------------- scan phase C: block scan + offset -> ptr, cursor ---------
__global__ void k_scanC()
{
    __shared__ int s[256];
    int t = threadIdx.x;
    int b = blockIdx.x;
    int i = b * 256 + t;
    int mine = (i < NNODES) ? g_deg[i] : 0;
    s[t] = mine;
    __syncthreads();
    for (int off = 1; off < 256; off <<= 1) {
        int v = (t >= off) ? s[t - off] : 0;
        __syncthreads();
        s[t] += v;
        __syncthreads();
    }
    int excl = s[t] - mine + ((b > 0) ? g_part[b - 1] : 0);
    if (i < NNODES) { g_ptr[i] = excl; g_cur[i] = excl; }
}

// ---------------- permute edges into dst-grouped (src, w) pairs ------------
__global__ void k_permute(const void* __restrict__ ei_raw,
                          const float* __restrict__ w, int E)
{
    int e = blockIdx.x * blockDim.x + threadIdx.x;
    if (e >= E) return;
    int s, d;
    if (g_is64) {
        const long long* ei = reinterpret_cast<const long long*>(ei_raw);
        s = (int)ei[e];  d = (int)ei[E + e];
    } else {
        const int* ei = reinterpret_cast<const int*>(ei_raw);
        s = ei[e];  d = ei[E + e];
    }
    float wt = __ldg(w + e);
    int pos = atomicAdd(&g_cur[d], 1);
    if (pos < EMAX) g_csr[pos] = make_int2(s, __float_as_int(wt));
}

// ---------------- segment sum: node = sum_e w_e * f(src row) ---------------
// layer 0: f = identity over users/items virtual concat  -> write g_B
// layer 1: f = relu over g_B                             -> write g_A
__global__ void k_seg(const float* __restrict__ users,
                      const float* __restrict__ items, int layer)
{
    int tid = blockIdx.x * blockDim.x + threadIdx.x;
    int node = tid >> 4;
    if (node >= NNODES) return;
    const int c = (tid & 15) << 2;

    const int beg = g_ptr[node];
    const int deg = g_deg[node];

    float4 acc = make_float4(0.f, 0.f, 0.f, 0.f);
    int i = 0;
    for (; i + 2 <= deg; i += 2) {
        int2 e0 = g_csr[beg + i];
        int2 e1 = g_csr[beg + i + 1];
        float4 v0, v1;
        if (layer == 0) {
            const float* p0 = (e0.x < NUSERS)
                ? users + (size_t)e0.x * DIM
                : items + (size_t)(e0.x - NUSERS) * DIM;
            const float* p1 = (e1.x < NUSERS)
                ? users + (size_t)e1.x * DIM
                : items + (size_t)(e1.x - NUSERS) * DIM;
            v0 = *reinterpret_cast<const float4*>(p0 + c);
            v1 = *reinterpret_cast<const float4*>(p1 + c);
        } else {
            v0 = *reinterpret_cast<const float4*>(g_B + (size_t)e0.x * DIM + c);
            v1 = *reinterpret_cast<const float4*>(g_B + (size_t)e1.x * DIM + c);
            v0.x = fmaxf(v0.x, 0.f); v0.y = fmaxf(v0.y, 0.f);
            v0.z = fmaxf(v0.z, 0.f); v0.w = fmaxf(v0.w, 0.f);
            v1.x = fmaxf(v1.x, 0.f); v1.y = fmaxf(v1.y, 0.f);
            v1.z = fmaxf(v1.z, 0.f); v1.w = fmaxf(v1.w, 0.f);
        }
        float w0 = __int_as_float(e0.y);
        float w1 = __int_as_float(e1.y);
        acc.x = fmaf(v0.x, w0, acc.x); acc.y = fmaf(v0.y, w0, acc.y);
        acc.z = fmaf(v0.z, w0, acc.z); acc.w = fmaf(v0.w, w0, acc.w);
        acc.x = fmaf(v1.x, w1, acc.x); acc.y = fmaf(v1.y, w1, acc.y);
        acc.z = fmaf(v1.z, w1, acc.z); acc.w = fmaf(v1.w, w1, acc.w);
    }
    if (i < deg) {
        int2 e0 = g_csr[beg + i];
        float4 v0;
        if (layer == 0) {
            const float* p0 = (e0.x < NUSERS)
                ? users + (size_t)e0.x * DIM
                : items + (size_t)(e0.x - NUSERS) * DIM;
            v0 = *reinterpret_cast<const float4*>(p0 + c);
        } else {
            v0 = *reinterpret_cast<const float4*>(g_B + (size_t)e0.x * DIM + c);
            v0.x = fmaxf(v0.x, 0.f); v0.y = fmaxf(v0.y, 0.f);
            v0.z = fmaxf(v0.z, 0.f); v0.w = fmaxf(v0.w, 0.f);
        }
        float w0 = __int_as_float(e0.y);
        acc.x = fmaf(v0.x, w0, acc.x); acc.y = fmaf(v0.y, w0, acc.y);
        acc.z = fmaf(v0.z, w0, acc.z); acc.w = fmaf(v0.w, w0, acc.w);
    }

    float* dst = layer ? g_A : g_B;
    *reinterpret_cast<float4*>(dst + (size_t)node * DIM + c) = acc;
}

// ------- final: a = (orig + relu(B) + relu(A))/3; out = a@W^T + b ----------
// 64x64 tile per block; 4x4 register tile; float4 LDS both operands.
__global__ void __launch_bounds__(256)
k_final(const float* __restrict__ W, const float* __restrict__ b,
        const float* __restrict__ users, const float* __restrict__ items,
        float* __restrict__ out)
{
    __shared__ float Wt[DIM][DIM + 4];
    __shared__ float aT[DIM][DIM + 4];
    __shared__ float sb[DIM];

    const int t = threadIdx.x;
    for (int idx = t; idx < DIM * DIM; idx += 256) {
        int j = idx >> 6, k = idx & 63;
        Wt[k][j] = W[idx];
    }
    if (t < DIM) sb[t] = b[t];

    const int base = blockIdx.x * 64;

    {
        const int rowL  = t >> 2;
        const int row   = base + rowL;
        const int cbase = (t & 3) * 16;
        if (row < NNODES) {
            const float* orig_row = (row < NUSERS)
                ? users + (size_t)row * DIM
                : items + (size_t)(row - NUSERS) * DIM;
            float* copy_dst = (row < NUSERS)
                ? out + (size_t)NUSERS * DIM + (size_t)row * DIM
                : out + (size_t)2 * NUSERS * DIM + (size_t)NITEMS * DIM
                      + (size_t)(row - NUSERS) * DIM;
#pragma unroll
            for (int g = 0; g < 4; g++) {
                const int col = cbase + 4 * g;
                float4 o  = *reinterpret_cast<const float4*>(orig_row + col);
                float4 va = *reinterpret_cast<const float4*>(
                                g_A + (size_t)row * DIM + col);
                float4 vb = *reinterpret_cast<const float4*>(
                                g_B + (size_t)row * DIM + col);
                aT[col + 0][rowL] =
                    (o.x + fmaxf(vb.x, 0.f) + fmaxf(va.x, 0.f)) * (1.f / 3.f);
                aT[col + 1][rowL] =
                    (o.y + fmaxf(vb.y, 0.f) + fmaxf(va.y, 0.f)) * (1.f / 3.f);
                aT[col + 2][rowL] =
                    (o.z + fmaxf(vb.z, 0.f) + fmaxf(va.z, 0.f)) * (1.f / 3.f);
                aT[col + 3][rowL] =
                    (o.w + fmaxf(vb.w, 0.f) + fmaxf(va.w, 0.f)) * (1.f / 3.f);
                *reinterpret_cast<float4*>(copy_dst + col) = o;  // passthrough
            }
        } else {
#pragma unroll
            for (int g = 0; g < 4; g++) {
                const int col = cbase + 4 * g;
                aT[col + 0][rowL] = 0.f;
                aT[col + 1][rowL] = 0.f;
                aT[col + 2][rowL] = 0.f;
                aT[col + 3][rowL] = 0.f;
            }
        }
    }
    __syncthreads();

    const int ri = t >> 4;
    const int ci = t & 15;
    float acc[4][4] = {};

#pragma unroll
    for (int k = 0; k < DIM; k++) {
        float4 av = *reinterpret_cast<const float4*>(&aT[k][4 * ri]);
        float4 wv = *reinterpret_cast<const float4*>(&Wt[k][4 * ci]);
        acc[0][0] = fmaf(av.x, wv.x, acc[0][0]);
        acc[0][1] = fmaf(av.x, wv.y, acc[0][1]);
        acc[0][2] = fmaf(av.x, wv.z, acc[0][2]);
        acc[0][3] = fmaf(av.x, wv.w, acc[0][3]);
        acc[1][0] = fmaf(av.y, wv.x, acc[1][0]);
        acc[1][1] = fmaf(av.y, wv.y, acc[1][1]);
        acc[1][2] = fmaf(av.y, wv.z, acc[1][2]);
        acc[1][3] = fmaf(av.y, wv.w, acc[1][3]);
        acc[2][0] = fmaf(av.z, wv.x, acc[2][0]);
        acc[2][1] = fmaf(av.z, wv.y, acc[2][1]);
        acc[2][2] = fmaf(av.z, wv.z, acc[2][2]);
        acc[2][3] = fmaf(av.z, wv.w, acc[2][3]);
        acc[3][0] = fmaf(av.w, wv.x, acc[3][0]);
        acc[3][1] = fmaf(av.w, wv.y, acc[3][1]);
        acc[3][2] = fmaf(av.w, wv.z, acc[3][2]);
        acc[3][3] = fmaf(av.w, wv.w, acc[3][3]);
    }

    const float4 bias = *reinterpret_cast<const float4*>(&sb[4 * ci]);
#pragma unroll
    for (int r = 0; r < 4; r++) {
        const int row = base + 4 * ri + r;
        if (row >= NNODES) break;
        float4 s;
        s.x = acc[r][0] + bias.x;
        s.y = acc[r][1] + bias.y;
        s.z = acc[r][2] + bias.z;
        s.w = acc[r][3] + bias.w;
        float* dst = (row < NUSERS)
            ? out + (size_t)row * DIM
            : out + (size_t)2 * NUSERS * DIM + (size_t)(row - NUSERS) * DIM;
        *reinterpret_cast<float4*>(dst + 4 * ci) = s;
    }
}

// ---------------------------------------------------------------------------
extern "C" void kernel_launch(void* const* d_in, const int* in_sizes, int n_in,
                              void* d_out, int out_size)
{
    const void*  ei    = d_in[0];
    const float* w     = (const float*)d_in[1];
    const float* users = (const float*)d_in[2];
    const float* items = (const float*)d_in[3];
    const float* W     = (const float*)d_in[4];
    const float* b     = (const float*)d_in[5];
    float* out = (float*)d_out;

    const int E = in_sizes[1];        // edge_weight element count

    const int eb = (E + 255) / 256;
    const int segb = (NNODES * 16 + 255) / 256;

    k_zero<<<(NNODES + 255) / 256, 256>>>((const long long*)ei);
    k_hist<<<eb, 256>>>(ei, E);
    k_scanA<<<NB, 256>>>();
    k_scanB<<<1, 1024>>>();
    k_scanC<<<NB, 256>>>();
    k_permute<<<eb, 256>>>(ei, w, E);

    k_seg<<<segb, 256>>>(users, items, 0);   // inputs  -> B (raw sums)
    k_seg<<<segb, 256>>>(users, items, 1);   // relu(B) -> A (raw sums)

    k_final<<<(NNODES + 63) / 64, 256>>>(W, b, users, items, out);
}

// round 13
// speedup vs baseline: 1.3395x; 1.1133x over previous
#include <cuda_runtime.h>
#include <cuda_bf16.h>

#define NUSERS 100000
#define NITEMS 50000
#define NNODES 150000
#define DIM 64
#define EMAX 2000000
#define NB ((NNODES + 255) / 256)   // 586 scan blocks

// ---------------- scratch (device globals: allocation-free) ----------------
__device__ float g_B[NNODES * DIM];   // layer-1 output (raw sums)
__device__ int   g_deg[NNODES];       // per-dst degree
__device__ int   g_ptr[NNODES];       // CSR row start (exclusive prefix)
__device__ int   g_cur[NNODES];       // mutable cursor for permute
__device__ int2  g_csr[EMAX];         // (src, w_bits) grouped by dst
__device__ int   g_part[1024];        // scan partials
__device__ int   g_is64;              // edge_index dtype flag

// ---------------- zero degrees + dtype probe -------------------------------
__global__ void k_zero(const long long* __restrict__ ei_probe)
{
    int tid = blockIdx.x * blockDim.x + threadIdx.x;
    if (tid == 0) {
        int is64 = 1;
        for (int i = 0; i < 64; i++) {
            long long v = ei_probe[i];
            if (v < 0 || v >= (long long)NNODES) { is64 = 0; break; }
        }
        g_is64 = is64;
    }
    if (tid < NNODES) g_deg[tid] = 0;
}

// ---------------- histogram of dst -----------------------------------------
__global__ void k_hist(const void* __restrict__ ei_raw, int E)
{
    int e = blockIdx.x * blockDim.x + threadIdx.x;
    if (e >= E) return;
    int d;
    if (g_is64) d = (int)reinterpret_cast<const long long*>(ei_raw)[E + e];
    else        d = reinterpret_cast<const int*>(ei_raw)[E + e];
    atomicAdd(&g_deg[d], 1);
}

// ---------------- scan phase A: per-block partial sums ---------------------
__global__ void k_scanA()
{
    __shared__ int s[256];
    int t = threadIdx.x;
    int i = blockIdx.x * 256 + t;
    s[t] = (i < NNODES) ? g_deg[i] : 0;
    __syncthreads();
#pragma unroll
    for (int off = 128; off > 0; off >>= 1) {
        if (t < off) s[t] += s[t + off];
        __syncthreads();
    }
    if (t == 0) g_part[blockIdx.x] = s[0];
}

// ---------------- scan phase B: inclusive scan of partials (1 block) -------
__global__ void k_scanB()
{
    __shared__ int s[1024];
    int t = threadIdx.x;
    s[t] = (t < NB) ? g_part[t] : 0;
    __syncthreads();
    for (int off = 1; off < 1024; off <<= 1) {
        int v = (t >= off) ? s[t - off] : 0;
        __syncthreads();
        s[t] += v;
        __syncthreads();
    }
    if (t < NB) g_part[t] = s[t];   // inclusive partial sums
}

// ---------------- scan phase C: block scan + offset -> ptr, cursor ---------
__global__ void k_scanC()
{
    __shared__ int s[256];
    int t = threadIdx.x;
    int b = blockIdx.x;
    int i = b * 256 + t;
    int mine = (i < NNODES) ? g_deg[i] : 0;
    s[t] = mine;
    __syncthreads();
    for (int off = 1; off < 256; off <<= 1) {
        int v = (t >= off) ? s[t - off] : 0;
        __syncthreads();
        s[t] += v;
        __syncthreads();
    }
    int excl = s[t] - mine + ((b > 0) ? g_part[b - 1] : 0);
    if (i < NNODES) { g_ptr[i] = excl; g_cur[i] = excl; }
}

// ---------------- permute edges into dst-grouped (src, w) pairs ------------
__global__ void k_permute(const void* __restrict__ ei_raw,
                          const float* __restrict__ w, int E)
{
    int e = blockIdx.x * blockDim.x + threadIdx.x;
    if (e >= E) return;
    int s, d;
    if (g_is64) {
        const long long* ei = reinterpret_cast<const long long*>(ei_raw);
        s = (int)ei[e];  d = (int)ei[E + e];
    } else {
        const int* ei = reinterpret_cast<const int*>(ei_raw);
        s = ei[e];  d = ei[E + e];
    }
    float wt = __ldg(w + e);
    int pos = atomicAdd(&g_cur[d], 1);
    if (pos < EMAX) g_csr[pos] = make_int2(s, __float_as_int(wt));
}

// ---------------- seg0: B[node] = sum_e w_e * emb0[src]  (unroll 4) --------
__global__ void k_seg0(const float* __restrict__ users,
                       const float* __restrict__ items)
{
    int tid = blockIdx.x * blockDim.x + threadIdx.x;
    int node = tid >> 4;
    if (node >= NNODES) return;
    const int c = (tid & 15) << 2;

    const int beg = g_ptr[node];
    const int deg = g_deg[node];

    float4 acc = make_float4(0.f, 0.f, 0.f, 0.f);
    int i = 0;
    for (; i + 4 <= deg; i += 4) {
        int2 e0 = g_csr[beg + i];
        int2 e1 = g_csr[beg + i + 1];
        int2 e2 = g_csr[beg + i + 2];
        int2 e3 = g_csr[beg + i + 3];
        const float* p0 = (e0.x < NUSERS) ? users + (size_t)e0.x * DIM
                                          : items + (size_t)(e0.x - NUSERS) * DIM;
        const float* p1 = (e1.x < NUSERS) ? users + (size_t)e1.x * DIM
                                          : items + (size_t)(e1.x - NUSERS) * DIM;
        const float* p2 = (e2.x < NUSERS) ? users + (size_t)e2.x * DIM
                                          : items + (size_t)(e2.x - NUSERS) * DIM;
        const float* p3 = (e3.x < NUSERS) ? users + (size_t)e3.x * DIM
                                          : items + (size_t)(e3.x - NUSERS) * DIM;
        float4 v0 = *reinterpret_cast<const float4*>(p0 + c);
        float4 v1 = *reinterpret_cast<const float4*>(p1 + c);
        float4 v2 = *reinterpret_cast<const float4*>(p2 + c);
        float4 v3 = *reinterpret_cast<const float4*>(p3 + c);
        float w0 = __int_as_float(e0.y), w1 = __int_as_float(e1.y);
        float w2 = __int_as_float(e2.y), w3 = __int_as_float(e3.y);
        acc.x = fmaf(v0.x, w0, acc.x); acc.y = fmaf(v0.y, w0, acc.y);
        acc.z = fmaf(v0.z, w0, acc.z); acc.w = fmaf(v0.w, w0, acc.w);
        acc.x = fmaf(v1.x, w1, acc.x); acc.y = fmaf(v1.y, w1, acc.y);
        acc.z = fmaf(v1.z, w1, acc.z); acc.w = fmaf(v1.w, w1, acc.w);
        acc.x = fmaf(v2.x, w2, acc.x); acc.y = fmaf(v2.y, w2, acc.y);
        acc.z = fmaf(v2.z, w2, acc.z); acc.w = fmaf(v2.w, w2, acc.w);
        acc.x = fmaf(v3.x, w3, acc.x); acc.y = fmaf(v3.y, w3, acc.y);
        acc.z = fmaf(v3.z, w3, acc.z); acc.w = fmaf(v3.w, w3, acc.w);
    }
    for (; i < deg; i++) {
        int2 e0 = g_csr[beg + i];
        const float* p0 = (e0.x < NUSERS) ? users + (size_t)e0.x * DIM
                                          : items + (size_t)(e0.x - NUSERS) * DIM;
        float4 v0 = *reinterpret_cast<const float4*>(p0 + c);
        float w0 = __int_as_float(e0.y);
        acc.x = fmaf(v0.x, w0, acc.x); acc.y = fmaf(v0.y, w0, acc.y);
        acc.z = fmaf(v0.z, w0, acc.z); acc.w = fmaf(v0.w, w0, acc.w);
    }
    *reinterpret_cast<float4*>(g_B + (size_t)node * DIM + c) = acc;
}

// ----- fused seg1 + final: per block, 64 nodes ------------------------------
// Phase 1: 16 groups x 16 threads; group g aggregates nodes base+4g..+4g+3:
//   accA = sum_e w_e * relu(B[src]); aT[:, rowL] = (orig + relu(B[node])
//   + relu(accA)) / 3; passthrough copy of orig.
// Phase 2: 64x64 GEMM tile, 4x4 register tile per thread (round-7 proven).
__global__ void __launch_bounds__(256)
k_seg1_final(const float* __restrict__ W, const float* __restrict__ b,
             const float* __restrict__ users, const float* __restrict__ items,
             float* __restrict__ out)
{
    __shared__ float Wt[DIM][DIM + 4];
    __shared__ float aT[DIM][DIM + 4];
    __shared__ float sb[DIM];

    const int t = threadIdx.x;
    for (int idx = t; idx < DIM * DIM; idx += 256) {
        int j = idx >> 6, k = idx & 63;
        Wt[k][j] = W[idx];
    }
    if (t < DIM) sb[t] = b[t];

    const int base = blockIdx.x * 64;
    const int grp  = t >> 4;          // 0..15
    const int c    = (t & 15) << 2;   // float col within row

#pragma unroll
    for (int n = 0; n < 4; n++) {
        const int rowL = grp * 4 + n;
        const int node = base + rowL;
        float4 av = make_float4(0.f, 0.f, 0.f, 0.f);
        if (node < NNODES) {
            const int beg = g_ptr[node];
            const int deg = g_deg[node];
            float4 acc = make_float4(0.f, 0.f, 0.f, 0.f);
            int i = 0;
            for (; i + 4 <= deg; i += 4) {
                int2 e0 = g_csr[beg + i];
                int2 e1 = g_csr[beg + i + 1];
                int2 e2 = g_csr[beg + i + 2];
                int2 e3 = g_csr[beg + i + 3];
                float4 v0 = *reinterpret_cast<const float4*>(
                                g_B + (size_t)e0.x * DIM + c);
                float4 v1 = *reinterpret_cast<const float4*>(
                                g_B + (size_t)e1.x * DIM + c);
                float4 v2 = *reinterpret_cast<const float4*>(
                                g_B + (size_t)e2.x * DIM + c);
                float4 v3 = *reinterpret_cast<const float4*>(
                                g_B + (size_t)e3.x * DIM + c);
                float w0 = __int_as_float(e0.y), w1 = __int_as_float(e1.y);
                float w2 = __int_as_float(e2.y), w3 = __int_as_float(e3.y);
                acc.x = fmaf(fmaxf(v0.x, 0.f), w0, acc.x);
                acc.y = fmaf(fmaxf(v0.y, 0.f), w0, acc.y);
                acc.z = fmaf(fmaxf(v0.z, 0.f), w0, acc.z);
                acc.w = fmaf(fmaxf(v0.w, 0.f), w0, acc.w);
                acc.x = fmaf(fmaxf(v1.x, 0.f), w1, acc.x);
                acc.y = fmaf(fmaxf(v1.y, 0.f), w1, acc.y);
                acc.z = fmaf(fmaxf(v1.z, 0.f), w1, acc.z);
                acc.w = fmaf(fmaxf(v1.w, 0.f), w1, acc.w);
                acc.x = fmaf(fmaxf(v2.x, 0.f), w2, acc.x);
                acc.y = fmaf(fmaxf(v2.y, 0.f), w2, acc.y);
                acc.z = fmaf(fmaxf(v2.z, 0.f), w2, acc.z);
                acc.w = fmaf(fmaxf(v2.w, 0.f), w2, acc.w);
                acc.x = fmaf(fmaxf(v3.x, 0.f), w3, acc.x);
                acc.y = fmaf(fmaxf(v3.y, 0.f), w3, acc.y);
                acc.z = fmaf(fmaxf(v3.z, 0.f), w3, acc.z);
                acc.w = fmaf(fmaxf(v3.w, 0.f), w3, acc.w);
            }
            for (; i < deg; i++) {
                int2 e0 = g_csr[beg + i];
                float4 v0 = *reinterpret_cast<const float4*>(
                                g_B + (size_t)e0.x * DIM + c);
                float w0 = __int_as_float(e0.y);
                acc.x = fmaf(fmaxf(v0.x, 0.f), w0, acc.x);
                acc.y = fmaf(fmaxf(v0.y, 0.f), w0, acc.y);
                acc.z = fmaf(fmaxf(v0.z, 0.f), w0, acc.z);
                acc.w = fmaf(fmaxf(v0.w, 0.f), w0, acc.w);
            }

            const float* orig_row = (node < NUSERS)
                ? users + (size_t)node * DIM
                : items + (size_t)(node - NUSERS) * DIM;
            float* copy_dst = (node < NUSERS)
                ? out + (size_t)NUSERS * DIM + (size_t)node * DIM
                : out + (size_t)2 * NUSERS * DIM + (size_t)NITEMS * DIM
                      + (size_t)(node - NUSERS) * DIM;
            float4 o  = *reinterpret_cast<const float4*>(orig_row + c);
            float4 vb = *reinterpret_cast<const float4*>(
                            g_B + (size_t)node * DIM + c);
            av.x = (o.x + fmaxf(vb.x, 0.f) + fmaxf(acc.x, 0.f)) * (1.f / 3.f);
            av.y = (o.y + fmaxf(vb.y, 0.f) + fmaxf(acc.y, 0.f)) * (1.f / 3.f);
            av.z = (o.z + fmaxf(vb.z, 0.f) + fmaxf(acc.z, 0.f)) * (1.f / 3.f);
            av.w = (o.w + fmaxf(vb.w, 0.f) + fmaxf(acc.w, 0.f)) * (1.f / 3.f);
            *reinterpret_cast<float4*>(copy_dst + c) = o;   // passthrough
        }
        aT[c + 0][rowL] = av.x;
        aT[c + 1][rowL] = av.y;
        aT[c + 2][rowL] = av.z;
        aT[c + 3][rowL] = av.w;
    }
    __syncthreads();

    // ---- GEMM phase: thread (ri, ci) -> rows 4ri..+3, cols 4ci..+3 ----
    const int ri = t >> 4;
    const int ci = t & 15;
    float acc[4][4] = {};

#pragma unroll
    for (int k = 0; k < DIM; k++) {
        float4 av = *reinterpret_cast<const float4*>(&aT[k][4 * ri]);
        float4 wv = *reinterpret_cast<const float4*>(&Wt[k][4 * ci]);
        acc[0][0] = fmaf(av.x, wv.x, acc[0][0]);
        acc[0][1] = fmaf(av.x, wv.y, acc[0][1]);
        acc[0][2] = fmaf(av.x, wv.z, acc[0][2]);
        acc[0][3] = fmaf(av.x, wv.w, acc[0][3]);
        acc[1][0] = fmaf(av.y, wv.x, acc[1][0]);
        acc[1][1] = fmaf(av.y, wv.y, acc[1][1]);
        acc[1][2] = fmaf(av.y, wv.z, acc[1][2]);
        acc[1][3] = fmaf(av.y, wv.w, acc[1][3]);
        acc[2][0] = fmaf(av.z, wv.x, acc[2][0]);
        acc[2][1] = fmaf(av.z, wv.y, acc[2][1]);
        acc[2][2] = fmaf(av.z, wv.z, acc[2][2]);
        acc[2][3] = fmaf(av.z, wv.w, acc[2][3]);
        acc[3][0] = fmaf(av.w, wv.x, acc[3][0]);
        acc[3][1] = fmaf(av.w, wv.y, acc[3][1]);
        acc[3][2] = fmaf(av.w, wv.z, acc[3][2]);
        acc[3][3] = fmaf(av.w, wv.w, acc[3][3]);
    }

    const float4 bias = *reinterpret_cast<const float4*>(&sb[4 * ci]);
#pragma unroll
    for (int r = 0; r < 4; r++) {
        const int row = base + 4 * ri + r;
        if (row >= NNODES) break;
        float4 s;
        s.x = acc[r][0] + bias.x;
        s.y = acc[r][1] + bias.y;
        s.z = acc[r][2] + bias.z;
        s.w = acc[r][3] + bias.w;
        float* dst = (row < NUSERS)
            ? out + (size_t)row * DIM
            : out + (size_t)2 * NUSERS * DIM + (size_t)(row - NUSERS) * DIM;
        *reinterpret_cast<float4*>(dst + 4 * ci) = s;
    }
}

// ---------------------------------------------------------------------------
extern "C" void kernel_launch(void* const* d_in, const int* in_sizes, int n_in,
                              void* d_out, int out_size)
{
    const void*  ei    = d_in[0];
    const float* w     = (const float*)d_in[1];
    const float* users = (const float*)d_in[2];
    const float* items = (const float*)d_in[3];
    const float* W     = (const float*)d_in[4];
    const float* b     = (const float*)d_in[5];
    float* out = (float*)d_out;

    const int E = in_sizes[1];        // edge_weight element count

    const int eb   = (E + 255) / 256;
    const int segb = (NNODES * 16 + 255) / 256;

    k_zero<<<(NNODES + 255) / 256, 256>>>((const long long*)ei);
    k_hist<<<eb, 256>>>(ei, E);
    k_scanA<<<NB, 256>>>();
    k_scanB<<<1, 1024>>>();
    k_scanC<<<NB, 256>>>();
    k_permute<<<eb, 256>>>(ei, w, E);

    k_seg0<<<segb, 256>>>(users, items);                    // inputs -> B

    k_seg1_final<<<(NNODES + 63) / 64, 256>>>(W, b, users, items, out);
}